// round 7
// baseline (speedup 1.0000x reference)
#include <cuda_runtime.h>
#include <cstddef>

#define Hd    50
#define WP    52          // padded row stride (floats), 208B = 13*16B
#define G4    200
#define Bsz   4096
#define Tt    256
#define TBtot (Tt*Bsz)    // 1048576
#define NCHUNK (TBtot/32) // 32768

// rec-kernel per-warp smem layout (floats)
#define HB 0              // h  [4][WP]
#define CB (4*WP)         // c  [4][WP]
#define PB (8*WP)         // preact [4 el][4 gate][WP]
#define BUFSZ (24*WP)     // 1248 floats

typedef unsigned long long ull;

// Inter-layer activations [t][b][50] (tb-major) + precomputed gate preacts
__device__ float g_ysA[(size_t)TBtot * Hd];
__device__ float g_ysB[(size_t)TBtot * Hd];
// XG layout: [t][slot s:8][b][28]  (slot s holds rows 25s..25s+24, padded to 28)
__device__ float g_xg[(size_t)TBtot * 224];

__device__ __forceinline__ ull ffma2(ull a, ull b, ull c) {
    ull d;
    asm("fma.rn.f32x2 %0, %1, %2, %3;" : "=l"(d) : "l"(a), "l"(b), "l"(c));
    return d;
}
__device__ __forceinline__ float f2sum(ull v) {
    float lo, hi;
    asm("mov.b64 {%0, %1}, %2;" : "=f"(lo), "=f"(hi) : "l"(v));
    return lo + hi;
}
__device__ __forceinline__ float sigf(float x) {
    return __fdividef(1.0f, 1.0f + __expf(-x));
}
__device__ __forceinline__ float tanhf_fast(float x) {
    return 1.0f - __fdividef(2.0f, __expf(2.0f * x) + 1.0f);
}

// ---------------- Phase A, layer 0: XG = x * w_ih0^T + b0 (rank-1) -------------
__global__ __launch_bounds__(224) void xg0_kernel(const float* __restrict__ x,
                                                  const float* __restrict__ w0,
                                                  const float* __restrict__ b0)
{
    __shared__ float xs[32];
    const int cid = blockIdx.x;            // chunk of 32 tb (same t)
    const int t   = cid >> 7;
    const int bb  = (cid & 127) << 5;
    const int k   = threadIdx.x;           // 0..223
    if (k < 32) xs[k] = x[(size_t)(bb + k) * Tt + t];
    const int s  = k / 28, kk = k - s * 28;
    const bool act = kk < 25;
    const int row = s * 25 + (act ? kk : 24);
    const float wv = w0[row], bv = b0[row];
    __syncthreads();
    float* base = g_xg + (((size_t)t * 8 + s) * Bsz + bb) * 28 + kk;
    #pragma unroll 8
    for (int el = 0; el < 32; el++)
        base[(size_t)el * 28] = act ? (xs[el] * wv + bv) : 0.0f;
}

// ---------------- Phase A, layers 1..4: XG = ys * W_ih^T + bias ----------------
// Warp w owns rows [25w, 25w+25) in registers; streams 32-element chunks.
__global__ __launch_bounds__(256, 2) void xgemm_kernel(const float* __restrict__ ys,
                                                       const float* __restrict__ w,
                                                       const float* __restrict__ bias)
{
    __shared__ float sin[32 * WP];
    const int tid  = threadIdx.x;
    const int wid  = tid >> 5;
    const int lane = tid & 31;
    const bool act = lane < 25;
    const int row  = 25 * wid + (act ? lane : 24);

    ull wreg[25];
    {
        const ull* wp = (const ull*)(w + row * Hd);   // 8B-aligned (row*200B)
        #pragma unroll
        for (int q = 0; q < 25; q++) wreg[q] = wp[q];
    }
    const float br = bias[row];

    int c = blockIdx.x;
    float pf[7];
    #pragma unroll
    for (int k = 0; k < 7; k++) {
        int idx = tid + 256 * k;
        pf[k] = (idx < 1600) ? ys[(size_t)c * 1600 + idx] : 0.0f;
    }

    for (; c < NCHUNK; c += gridDim.x) {
        __syncthreads();    // previous chunk's compute done reading sin
        #pragma unroll
        for (int k = 0; k < 7; k++) {
            int idx = tid + 256 * k;
            if (idx < 1600) { int el = idx / 50, j = idx - el * 50; sin[el * WP + j] = pf[k]; }
        }
        __syncthreads();
        int cn = c + gridDim.x;
        if (cn < NCHUNK) {
            #pragma unroll
            for (int k = 0; k < 7; k++) {
                int idx = tid + 256 * k;
                if (idx < 1600) pf[k] = ys[(size_t)cn * 1600 + idx];
            }
        }
        // output base: t = c>>7 constant per chunk; b = (c&127)*32
        const int t = c >> 7, bb = (c & 127) << 5;
        float* obase = g_xg + (((size_t)t * 8 + wid) * Bsz + bb) * 28 + (act ? lane : 24);

        #pragma unroll 2
        for (int el = 0; el < 32; el += 2) {
            const ulonglong2* h0 = (const ulonglong2*)(sin + el * WP);
            const ulonglong2* h1 = (const ulonglong2*)(sin + (el + 1) * WP);
            ull a0 = 0ull, a1 = 0ull;
            #pragma unroll
            for (int q = 0; q < 12; q++) {
                ulonglong2 v0 = h0[q], v1 = h1[q];
                a0 = ffma2(wreg[2*q], v0.x, a0); a0 = ffma2(wreg[2*q+1], v0.y, a0);
                a1 = ffma2(wreg[2*q], v1.x, a1); a1 = ffma2(wreg[2*q+1], v1.y, a1);
            }
            ull t0 = ((const ull*)h0)[24], t1 = ((const ull*)h1)[24];
            a0 = ffma2(wreg[24], t0, a0);
            a1 = ffma2(wreg[24], t1, a1);
            if (act) {
                obase[(size_t)el * 28]       = f2sum(a0) + br;
                obase[(size_t)(el + 1) * 28] = f2sum(a1) + br;
            }
        }
    }
}

// ---------------- Phase B: recurrence only (h-side dot + gates) ----------------
// Warp owns 4 batch elements; lane=(s,e): s in [0,8) owns rows [25s,25s+25), e in [0,4).
__global__ __launch_bounds__(256, 1)
void rec_kernel(const float* __restrict__ w_hh,
                float* __restrict__ ys_out,
                const float* __restrict__ fc_w,
                const float* __restrict__ fc_b,
                float* __restrict__ out)
{
    extern __shared__ float sm[];
    float* Wh   = sm;                  // [200][WP]
    float* wbuf = sm + G4 * WP;        // [8][BUFSZ]

    const int tid  = threadIdx.x;
    const int wid  = tid >> 5;
    const int lane = tid & 31;
    const int s    = lane >> 2;
    const int e    = lane & 3;
    const int g    = s >> 1;
    const int u0   = (s & 1) * 25;

    float* wb = wbuf + wid * BUFSZ;
    const int b0 = blockIdx.x * 32 + wid * 4;

    // Wh with zeroed pads (cols 50,51) so full 13-pair dot is exact
    for (int i = tid; i < G4 * WP; i += 256) {
        int r = i / WP, j = i - r * WP;
        Wh[i] = (j < Hd) ? w_hh[r * Hd + j] : 0.0f;
    }
    for (int i = lane; i < BUFSZ; i += 32) wb[i] = 0.0f;   // h/c pads stay 0 forever
    __syncthreads();

    const float* xbase = g_xg + ((size_t)s * Bsz + (b0 + e)) * 28;

    for (int t = 0; t < Tt; t++) {
        // ---- XG prefetch (LDG, consumed after the dot; latency hidden) ----
        const float4* xp = (const float4*)(xbase + (size_t)t * 8 * Bsz * 28);
        float xgf[28];
        #pragma unroll
        for (int q = 0; q < 7; q++) {
            float4 v = xp[q];
            xgf[4*q] = v.x; xgf[4*q+1] = v.y; xgf[4*q+2] = v.z; xgf[4*q+3] = v.w;
        }

        // ---- h(t-1) into registers: 13 x ulonglong2 = floats 0..51 (pads=0) ----
        ulonglong2 h2[13];
        {
            const ulonglong2* hp = (const ulonglong2*)(wb + HB + e * WP);
            #pragma unroll
            for (int q = 0; q < 13; q++) h2[q] = hp[q];
        }

        // ---- recurrent dot: 25 rows x 52 (pads contribute 0) ----
        ull acc[25];
        #pragma unroll
        for (int r = 0; r < 25; r++) {
            const ulonglong2* wr = (const ulonglong2*)(Wh + (25 * s + r) * WP);
            ull a = 0ull;
            #pragma unroll
            for (int q = 0; q < 13; q++) {
                ulonglong2 wv = wr[q];
                a = ffma2(wv.x, h2[q].x, a);
                a = ffma2(wv.y, h2[q].y, a);
            }
            acc[r] = a;
        }

        // ---- finalize preacts = dot + XG ----
        #pragma unroll
        for (int r = 0; r < 25; r++)
            wb[PB + (e * 4 + g) * WP + u0 + r] = f2sum(acc[r]) + xgf[r];
        __syncwarp();

        // ---- pointwise gates + state update (200 items over 32 lanes) ----
        #pragma unroll
        for (int k = 0; k < 7; k++) {
            int item = lane + 32 * k;
            if (item < 200) {
                int ee = item / Hd, u = item - ee * Hd;
                float pi = wb[PB + (ee * 4 + 0) * WP + u];
                float pf = wb[PB + (ee * 4 + 1) * WP + u];
                float pg = wb[PB + (ee * 4 + 2) * WP + u];
                float po = wb[PB + (ee * 4 + 3) * WP + u];
                float cc = wb[CB + ee * WP + u];
                cc = sigf(pf) * cc + sigf(pi) * tanhf_fast(pg);
                wb[CB + ee * WP + u] = cc;
                wb[HB + ee * WP + u] = sigf(po) * tanhf_fast(cc);
            }
        }
        __syncwarp();

        // ---- coalesced ys(t) write ----
        if (ys_out != nullptr) {
            float* dst = ys_out + ((size_t)t * Bsz + b0) * Hd;
            #pragma unroll
            for (int k = 0; k < 7; k++) {
                int idx = lane + 32 * k;
                if (idx < 200) {
                    int ee = idx / Hd, jj = idx - ee * Hd;
                    dst[idx] = wb[HB + ee * WP + jj];
                }
            }
        }
    }

    // ---- FC head (last layer only) ----
    if (out != nullptr && lane < 4) {
        float sres = fc_b[0];
        #pragma unroll 10
        for (int j = 0; j < Hd; j++) sres += wb[HB + lane * WP + j] * fc_w[j];
        out[b0 + lane] = sres;
    }
}

extern "C" void kernel_launch(void* const* d_in, const int* in_sizes, int n_in,
                              void* d_out, int out_size)
{
    const float* x     = (const float*)d_in[0];  // [B,T,1]
    const float* w_ih0 = (const float*)d_in[1];  // [200,1]
    const float* w_hh0 = (const float*)d_in[2];  // [200,50]
    const float* b0    = (const float*)d_in[3];  // [200]
    const float* w_ih  = (const float*)d_in[4];  // [4,200,50]
    const float* w_hh  = (const float*)d_in[5];  // [4,200,50]
    const float* b     = (const float*)d_in[6];  // [4,200]
    const float* fc_w  = (const float*)d_in[7];  // [1,50]
    const float* fc_b  = (const float*)d_in[8];  // [1]
    float* out = (float*)d_out;

    float *ysA = nullptr, *ysB = nullptr;
    cudaGetSymbolAddress((void**)&ysA, g_ysA);
    cudaGetSymbolAddress((void**)&ysB, g_ysB);

    const int smemB = (G4 * WP + 8 * BUFSZ) * (int)sizeof(float);
    cudaFuncSetAttribute(rec_kernel, cudaFuncAttributeMaxDynamicSharedMemorySize, smemB);

    // Layer 0
    xg0_kernel<<<NCHUNK, 224>>>(x, w_ih0, b0);
    rec_kernel<<<128, 256, smemB>>>(w_hh0, ysA, nullptr, nullptr, nullptr);

    // Layers 1..3
    const float* src = ysA;
    float* dst = ysB;
    for (int l = 0; l < 3; l++) {
        xgemm_kernel<<<296, 256>>>(src, w_ih + (size_t)l * G4 * Hd, b + (size_t)l * G4);
        rec_kernel<<<128, 256, smemB>>>(w_hh + (size_t)l * G4 * Hd, dst, nullptr, nullptr, nullptr);
        const float* tmp = dst; dst = (float*)src; src = tmp;
    }

    // Layer 4: fused FC head
    xgemm_kernel<<<296, 256>>>(src, w_ih + (size_t)3 * G4 * Hd, b + (size_t)3 * G4);
    rec_kernel<<<128, 256, smemB>>>(w_hh + (size_t)3 * G4 * Hd, nullptr, fc_w, fc_b, out);
}